// round 4
// baseline (speedup 1.0000x reference)
#include <cuda_runtime.h>
#include <cstdint>

#define NN 100000
#define EMAX 1600000
#define D 64
#define NB ((NN + 511) / 512)   // 196 scan blocks

// Scratch (device globals; no allocation allowed)
__device__ __align__(16) float g_agg[(size_t)NN * D];
__device__ __align__(16) float g_h[(size_t)NN * D];
__device__ int g_cnt[NN];
__device__ int g_fill[NN];
__device__ int g_row[NN + 1];
__device__ int g_bsum[NB];
__device__ int g_boff[NB];
__device__ int g_src[EMAX];
__device__ int g_dst[EMAX];
__device__ int g_eidx[EMAX];
__device__ int g_is64;

// ---------------------------------------------------------------------------
// dtype probe: reference is JAX (x64 usually disabled) so edge_index is most
// likely int32 despite the reference source saying int64. If it really were
// int64 with node ids < 2^31, every odd 32-bit word is a zero high-word.
// OR-reduce 2048 sampled odd words: 0 -> int64 layout, nonzero -> int32.
// ---------------------------------------------------------------------------
__global__ void detect_kernel(const int* __restrict__ ei32, int E) {
    __shared__ int sm[256];
    int acc = 0;
    // sample odd words across the buffer (2E int32 words if int32; 4E if int64,
    // but reading the first 2E words is safe in either case)
    for (int i = threadIdx.x; i < 2048; i += 256) {
        long long w = (long long)i * (2LL * E / 2048) | 1LL;  // odd index
        acc |= ei32[w];
    }
    sm[threadIdx.x] = acc;
    __syncthreads();
    for (int off = 128; off > 0; off >>= 1) {
        if (threadIdx.x < off) sm[threadIdx.x] |= sm[threadIdx.x + off];
        __syncthreads();
    }
    if (threadIdx.x == 0) g_is64 = (sm[0] == 0) ? 1 : 0;
}

__global__ void zero_kernel() {
    int i = blockIdx.x * blockDim.x + threadIdx.x;
    if (i < NN) { g_cnt[i] = 0; g_fill[i] = 0; }
}

// edge_index -> int32 src/dst + per-dst degree count (dtype-adaptive, clamped)
__global__ void prep_kernel(const int* __restrict__ ei32, int E) {
    int t = blockIdx.x * blockDim.x + threadIdx.x;
    if (t >= E) return;
    int s, d;
    if (g_is64) {
        const long long* ei = (const long long*)ei32;
        s = (int)ei[t];
        d = (int)ei[(size_t)E + t];
    } else {
        s = ei32[t];
        d = ei32[(size_t)E + t];
    }
    // defensive clamp: never produce an out-of-range index (trap-proof)
    if ((unsigned)s >= NN) s = 0;
    if ((unsigned)d >= NN) d = 0;
    g_src[t] = s;
    g_dst[t] = d;
    atomicAdd(&g_cnt[d], 1);
}

// ---- 3-pass exclusive scan of g_cnt -> g_row (rowstart), g_row[NN] = E ----
__global__ void scan1_kernel() {               // per-block reduce
    __shared__ int sm[512];
    int i = blockIdx.x * 512 + threadIdx.x;
    sm[threadIdx.x] = (i < NN) ? g_cnt[i] : 0;
    __syncthreads();
    for (int off = 256; off > 0; off >>= 1) {
        if (threadIdx.x < off) sm[threadIdx.x] += sm[threadIdx.x + off];
        __syncthreads();
    }
    if (threadIdx.x == 0) g_bsum[blockIdx.x] = sm[0];
}

__global__ void scan2_kernel() {               // scan of 196 block sums
    __shared__ int sm[256];
    int v = (threadIdx.x < NB) ? g_bsum[threadIdx.x] : 0;
    sm[threadIdx.x] = v;
    __syncthreads();
    for (int off = 1; off < 256; off <<= 1) {
        int t = (threadIdx.x >= off) ? sm[threadIdx.x - off] : 0;
        __syncthreads();
        sm[threadIdx.x] += t;
        __syncthreads();
    }
    if (threadIdx.x < NB) g_boff[threadIdx.x] = sm[threadIdx.x] - v;
}

__global__ void scan3_kernel() {               // per-block scan + offset
    __shared__ int sm[512];
    int i = blockIdx.x * 512 + threadIdx.x;
    int v = (i < NN) ? g_cnt[i] : 0;
    sm[threadIdx.x] = v;
    __syncthreads();
    for (int off = 1; off < 512; off <<= 1) {
        int t = (threadIdx.x >= off) ? sm[threadIdx.x - off] : 0;
        __syncthreads();
        sm[threadIdx.x] += t;
        __syncthreads();
    }
    int incl = sm[threadIdx.x];
    int boff = g_boff[blockIdx.x];
    if (i < NN) g_row[i] = boff + incl - v;
    if (i == NN - 1) g_row[NN] = boff + incl;
}

// scatter edges into CSR slots (int atomics only, all bounded)
__global__ void fill_kernel(int E) {
    int t = blockIdx.x * blockDim.x + threadIdx.x;
    if (t >= E) return;
    int d = g_dst[t];
    int ofs = atomicAdd(&g_fill[d], 1);
    g_eidx[g_row[d] + ofs] = g_src[t];
}

// ---------------------------------------------------------------------------
// aggregate: one warp per node; gather x[src] rows, register-accumulate,
// fused mean. No float atomics anywhere.
// ---------------------------------------------------------------------------
__global__ void aggregate_kernel(const float* __restrict__ xin,
                                 float* __restrict__ aggout) {
    int warp = (blockIdx.x * blockDim.x + threadIdx.x) >> 5;
    if (warp >= NN) return;                 // uniform per warp
    int lane = threadIdx.x & 31;
    int r = lane & 15;                      // float4 slot in 64-float row
    int half = lane >> 4;                   // which of 2 neighbors per step

    int rs = g_row[warp], re = g_row[warp + 1];
    const float4* __restrict__ x4 = (const float4*)xin;
    float4 acc = make_float4(0.f, 0.f, 0.f, 0.f);

    for (int j = rs; j < re; j += 32) {
        int idx = 0;
        if (j + lane < re) idx = g_eidx[j + lane];   // coalesced index load
        int m = min(32, re - j);
        if (m == 32) {
#pragma unroll
            for (int k = 0; k < 32; k += 2) {
                int s = __shfl_sync(0xffffffffu, idx, k + half);
                float4 v = x4[(size_t)s * 16 + r];
                acc.x += v.x; acc.y += v.y; acc.z += v.z; acc.w += v.w;
            }
        } else {
            for (int k = 0; k < m; k += 2) {
                int which = k + half;
                int s = __shfl_sync(0xffffffffu, idx, which);
                if (which < m) {
                    float4 v = x4[(size_t)s * 16 + r];
                    acc.x += v.x; acc.y += v.y; acc.z += v.z; acc.w += v.w;
                }
            }
        }
    }
    // combine the two half-warp partials
    acc.x += __shfl_xor_sync(0xffffffffu, acc.x, 16);
    acc.y += __shfl_xor_sync(0xffffffffu, acc.y, 16);
    acc.z += __shfl_xor_sync(0xffffffffu, acc.z, 16);
    acc.w += __shfl_xor_sync(0xffffffffu, acc.w, 16);

    if (half == 0) {
        int deg = re - rs;
        float sc = 1.0f / (float)(deg > 0 ? deg : 1);
        acc.x *= sc; acc.y *= sc; acc.z *= sc; acc.w *= sc;
        ((float4*)aggout)[(size_t)warp * 16 + r] = acc;
    }
}

// ---------------------------------------------------------------------------
// fused node update: out = relu( agg @ Wl^T + bl + xin @ Wr^T )
// (agg already holds the mean)
// ---------------------------------------------------------------------------
__global__ void gemm_kernel(const float* __restrict__ agg,
                            const float* __restrict__ xin,
                            const float* __restrict__ Wl,
                            const float* __restrict__ bl,
                            const float* __restrict__ Wr,
                            float* __restrict__ out) {
    __shared__ float As[64][68];   // [node][k], padded
    __shared__ float Bs[64][68];   // [k][j],   padded (Bs[k][j] = W[j][k])

    int tid = threadIdx.x;
    int tx  = tid & 15;
    int ty  = tid >> 4;
    int node0 = blockIdx.x * 64;

    float acc[4][4];
#pragma unroll
    for (int i = 0; i < 4; i++)
#pragma unroll
        for (int j = 0; j < 4; j++) acc[i][j] = 0.0f;

#pragma unroll
    for (int phase = 0; phase < 2; phase++) {
        const float* __restrict__ A = phase ? xin : agg;
        const float* __restrict__ W = phase ? Wr : Wl;

        for (int i = tid; i < 64 * 64; i += 256) {
            int j = i >> 6, k = i & 63;
            Bs[k][j] = W[i];
        }
        for (int i = tid; i < 64 * 16; i += 256) {
            int n = i >> 4, kq = i & 15;
            int node = node0 + n;
            float4 v = make_float4(0.f, 0.f, 0.f, 0.f);
            if (node < NN)
                v = ((const float4*)A)[(size_t)node * 16 + kq];
            *(float4*)&As[n][kq << 2] = v;
        }
        __syncthreads();

#pragma unroll 8
        for (int k = 0; k < 64; k++) {
            float4 b4 = *(const float4*)&Bs[k][tx << 2];
            float a0 = As[(ty << 2) + 0][k];
            float a1 = As[(ty << 2) + 1][k];
            float a2 = As[(ty << 2) + 2][k];
            float a3 = As[(ty << 2) + 3][k];
            acc[0][0] = fmaf(a0, b4.x, acc[0][0]);
            acc[0][1] = fmaf(a0, b4.y, acc[0][1]);
            acc[0][2] = fmaf(a0, b4.z, acc[0][2]);
            acc[0][3] = fmaf(a0, b4.w, acc[0][3]);
            acc[1][0] = fmaf(a1, b4.x, acc[1][0]);
            acc[1][1] = fmaf(a1, b4.y, acc[1][1]);
            acc[1][2] = fmaf(a1, b4.z, acc[1][2]);
            acc[1][3] = fmaf(a1, b4.w, acc[1][3]);
            acc[2][0] = fmaf(a2, b4.x, acc[2][0]);
            acc[2][1] = fmaf(a2, b4.y, acc[2][1]);
            acc[2][2] = fmaf(a2, b4.z, acc[2][2]);
            acc[2][3] = fmaf(a2, b4.w, acc[2][3]);
            acc[3][0] = fmaf(a3, b4.x, acc[3][0]);
            acc[3][1] = fmaf(a3, b4.y, acc[3][1]);
            acc[3][2] = fmaf(a3, b4.z, acc[3][2]);
            acc[3][3] = fmaf(a3, b4.w, acc[3][3]);
        }
        __syncthreads();
    }

    float4 bv = ((const float4*)bl)[tx];
#pragma unroll
    for (int i = 0; i < 4; i++) {
        int node = node0 + (ty << 2) + i;
        if (node < NN) {
            float4 o;
            o.x = fmaxf(acc[i][0] + bv.x, 0.0f);
            o.y = fmaxf(acc[i][1] + bv.y, 0.0f);
            o.z = fmaxf(acc[i][2] + bv.z, 0.0f);
            o.w = fmaxf(acc[i][3] + bv.w, 0.0f);
            ((float4*)out)[(size_t)node * 16 + tx] = o;
        }
    }
}

// ---------------------------------------------------------------------------
extern "C" void kernel_launch(void* const* d_in, const int* in_sizes, int n_in,
                              void* d_out, int out_size) {
    const float* x   = (const float*)d_in[0];
    const int*   ei  = (const int*)d_in[1];    // int32 or int64; probed on device
    const float* W1l = (const float*)d_in[2];
    const float* b1l = (const float*)d_in[3];
    const float* W1r = (const float*)d_in[4];
    const float* W2l = (const float*)d_in[5];
    const float* b2l = (const float*)d_in[6];
    const float* W2r = (const float*)d_in[7];
    int E = in_sizes[1] / 2;
    if (E > EMAX) E = EMAX;

    void *agg_p = nullptr, *h_p = nullptr;
    cudaGetSymbolAddress(&agg_p, g_agg);
    cudaGetSymbolAddress(&h_p,   g_h);
    float* agg = (float*)agg_p;
    float* h   = (float*)h_p;

    // CSR build
    detect_kernel<<<1, 256>>>(ei, E);
    zero_kernel<<<(NN + 255) / 256, 256>>>();
    prep_kernel<<<(E + 255) / 256, 256>>>(ei, E);
    scan1_kernel<<<NB, 512>>>();
    scan2_kernel<<<1, 256>>>();
    scan3_kernel<<<NB, 512>>>();
    fill_kernel<<<(E + 255) / 256, 256>>>(E);

    // Layer 1
    aggregate_kernel<<<(NN * 32 + 255) / 256, 256>>>(x, agg);
    gemm_kernel<<<(NN + 63) / 64, 256>>>(agg, x, W1l, b1l, W1r, h);

    // Layer 2
    aggregate_kernel<<<(NN * 32 + 255) / 256, 256>>>(h, agg);
    gemm_kernel<<<(NN + 63) / 64, 256>>>(agg, h, W2l, b2l, W2r, (float*)d_out);
}